// round 1
// baseline (speedup 1.0000x reference)
#include <cuda_runtime.h>

#define NPIX 9216            // H*W = 96*96
#define BATCH 2
#define TOT (BATCH*NPIX)     // 18432

// Scratch (allocation-free rule: __device__ globals)
__device__ float g_p[TOT];      // channel-0 softmax per pixel
__device__ float g_out0[TOT];   // out[b,0,n] = T/S

// exp(t) for t in (-1,1): degree-7 Taylor, abs err <= ~3e-5
__device__ __forceinline__ float exp_poly(float t) {
    float r = 1.0f / 5040.0f;
    r = fmaf(r, t, 1.0f / 720.0f);
    r = fmaf(r, t, 1.0f / 120.0f);
    r = fmaf(r, t, 1.0f / 24.0f);
    r = fmaf(r, t, 1.0f / 6.0f);
    r = fmaf(r, t, 0.5f);
    r = fmaf(r, t, 1.0f);
    r = fmaf(r, t, 1.0f);
    return r;
}

// Kernel 1: p[b,n] = softmax_c(x)[b,0,n] = sigmoid(x0 - x1)
__global__ void k_prep(const float* __restrict__ x) {
    int i = blockIdx.x * blockDim.x + threadIdx.x;
    if (i >= TOT) return;
    int b = i / NPIX;
    int n = i - b * NPIX;
    float x0 = x[(size_t)(b * 2 + 0) * NPIX + n];
    float x1 = x[(size_t)(b * 2 + 1) * NPIX + n];
    g_p[i] = 1.0f / (1.0f + __expf(x1 - x0));
}

// Kernel 2: one block per attention row.
//   e_m = exp(a_n * p_m); S = sum e; T = sum p*e
//   attn[row, m] = e_m / S ; g_out0[row] = T/S
__global__ void __launch_bounds__(256, 3) k_attn(float* __restrict__ attn) {
    const int row = blockIdx.x;             // 0 .. TOT-1
    const int b = row / NPIX;
    const int tid = threadIdx.x;

    const float4* __restrict__ p4 =
        reinterpret_cast<const float4*>(g_p + b * NPIX);
    const float a = 2.0f * g_p[row] - 1.0f;

    float4 e[9];                             // 36 elems/thread, registers
    float S = 0.0f, T = 0.0f;

#pragma unroll
    for (int k = 0; k < 9; k++) {
        float4 pv = p4[tid + k * 256];       // coalesced, L2-resident
        float ex = exp_poly(a * pv.x);
        float ey = exp_poly(a * pv.y);
        float ez = exp_poly(a * pv.z);
        float ew = exp_poly(a * pv.w);
        e[k].x = ex; e[k].y = ey; e[k].z = ez; e[k].w = ew;
        S += ex + ey + ez + ew;
        T = fmaf(pv.x, ex, T);
        T = fmaf(pv.y, ey, T);
        T = fmaf(pv.z, ez, T);
        T = fmaf(pv.w, ew, T);
    }

    // block reduce S, T (8 warps)
    __shared__ float sS[8], sT[8];
#pragma unroll
    for (int o = 16; o > 0; o >>= 1) {
        S += __shfl_xor_sync(0xFFFFFFFFu, S, o);
        T += __shfl_xor_sync(0xFFFFFFFFu, T, o);
    }
    int lane = tid & 31, wid = tid >> 5;
    if (lane == 0) { sS[wid] = S; sT[wid] = T; }
    __syncthreads();
    float St = sS[0] + sS[1] + sS[2] + sS[3] + sS[4] + sS[5] + sS[6] + sS[7];
    float invS = 1.0f / St;

    if (tid == 0) {
        float Tt = sT[0] + sT[1] + sT[2] + sT[3] + sT[4] + sT[5] + sT[6] + sT[7];
        g_out0[row] = Tt * invS;
    }

    float4* __restrict__ out4 =
        reinterpret_cast<float4*>(attn + (size_t)row * NPIX);
#pragma unroll
    for (int k = 0; k < 9; k++) {
        float4 v;
        v.x = e[k].x * invS;
        v.y = e[k].y * invS;
        v.z = e[k].z * invS;
        v.w = e[k].w * invS;
        out4[tid + k * 256] = v;             // coalesced 128B stores
    }
}

// Kernel 3: epilogue y = sigmoid(w0*pre0 + w1*pre1 + cb)
__global__ void k_epi(const float* __restrict__ w,
                      const float* __restrict__ cb,
                      const float* __restrict__ gm,
                      float* __restrict__ y) {
    int i = blockIdx.x * blockDim.x + threadIdx.x;
    if (i >= TOT) return;
    float p = g_p[i];
    float o0 = g_out0[i];
    float g = gm[0];
    float pre0 = fmaf(g, o0, p);
    float pre1 = fmaf(g, 1.0f - o0, 1.0f - p);
    float t = fmaf(w[0], pre0, fmaf(w[1], pre1, cb[0]));
    y[i] = 1.0f / (1.0f + __expf(-t));
}

extern "C" void kernel_launch(void* const* d_in, const int* in_sizes, int n_in,
                              void* d_out, int out_size) {
    const float* x  = (const float*)d_in[0];   // [2,2,96,96]
    const float* w  = (const float*)d_in[1];   // [2]
    const float* cb = (const float*)d_in[2];   // [1]
    const float* gm = (const float*)d_in[3];   // [1]
    float* out = (float*)d_out;                // [18432 y | 2*9216*9216 attn]

    k_prep<<<(TOT + 255) / 256, 256>>>(x);
    k_attn<<<TOT, 256>>>(out + TOT);
    k_epi<<<(TOT + 255) / 256, 256>>>(w, cb, gm, out);
}